// round 2
// baseline (speedup 1.0000x reference)
#include <cuda_runtime.h>
#include <math.h>

#define NRAYS 16384
#define MAXS 128

// ---------------- scratch (device globals; no allocation allowed) ----------
__device__ float g_dirs[NRAYS * 3];
__device__ float g_d[NRAYS * MAXS];
__device__ float g_sdf[NRAYS * MAXS];
__device__ float g_dfine[NRAYS * 16];
__device__ float g_sdff[NRAYS * 16];

// ---------------- math helpers (match jax.nn numerics) ---------------------
__device__ __forceinline__ float softplus_f(float x) {
    // jax.nn.softplus = logaddexp(x, 0) = max(x,0) + log1p(exp(-|x|))
    return fmaxf(x, 0.0f) + log1pf(expf(-fabsf(x)));
}
__device__ __forceinline__ float sigmoid_f(float x) {
    return 1.0f / (1.0f + expf(-x));
}

// ---------------- init: normalize dirs, fill coarse d ----------------------
__global__ void init_kernel(const float* __restrict__ rd,
                            const float* __restrict__ nearp,
                            const float* __restrict__ farp) {
    int r = blockIdx.x * blockDim.x + threadIdx.x;
    if (r >= NRAYS) return;
    float dx = rd[r * 3 + 0], dy = rd[r * 3 + 1], dz = rd[r * 3 + 2];
    float nrm = sqrtf(dx * dx + dy * dy + dz * dz);
    dx /= nrm; dy /= nrm; dz /= nrm;
    g_dirs[r * 3 + 0] = dx; g_dirs[r * 3 + 1] = dy; g_dirs[r * 3 + 2] = dz;
    float nr = nearp[r], fr = farp[r];
    for (int j = 0; j < 64; j++) {
        float t = (float)j / 63.0f;
        g_d[r * MAXS + j] = nr * (1.0f - t) + fr * t;
    }
}

// ---------------- SDF MLP eval --------------------------------------------
// mode 0: coarse (g_d, stride 128, 64 samples/ray -> g_sdf)
// mode 1: fine   (g_dfine, stride 16, 16 samples/ray -> g_sdff)
__global__ void sdf_kernel(const float* __restrict__ o,
                           const float* __restrict__ w1, const float* __restrict__ b1,
                           const float* __restrict__ w2, const float* __restrict__ b2,
                           const float* __restrict__ w3, const float* __restrict__ b3,
                           int mode, int npts) {
    __shared__ __align__(16) float w2t[64 * 64];  // transposed: w2t[j*64+k] = w2[k*64+j]
    __shared__ float w1s[192], b1s[64], b2s[64], w3s[64];
    __shared__ float b3s;

    int tid = threadIdx.x;
    for (int i = tid; i < 4096; i += blockDim.x) {
        w2t[(i & 63) * 64 + (i >> 6)] = w2[i];
    }
    for (int i = tid; i < 192; i += blockDim.x) w1s[i] = w1[i];
    if (tid < 64) { b1s[tid] = b1[tid]; b2s[tid] = b2[tid]; w3s[tid] = w3[tid]; }
    if (tid == 0) b3s = b3[0];
    __syncthreads();

    int p = blockIdx.x * blockDim.x + tid;
    if (p >= npts) return;

    const float* dvals = mode ? g_dfine : g_d;
    float* outp        = mode ? g_sdff  : g_sdf;
    int spr    = mode ? 16 : 64;
    int stride = mode ? 16 : MAXS;

    int ray = p / spr;
    int j   = p - ray * spr;
    float dv = dvals[ray * stride + j];

    float ox = o[ray * 3 + 0], oy = o[ray * 3 + 1], oz = o[ray * 3 + 2];
    float dx = g_dirs[ray * 3 + 0], dy = g_dirs[ray * 3 + 1], dz = g_dirs[ray * 3 + 2];
    float px = fmaf(dv, dx, ox), py = fmaf(dv, dy, oy), pz = fmaf(dv, dz, oz);

    // layer 1: 3 -> 64, softplus
    float h1[64];
#pragma unroll
    for (int q = 0; q < 64; q++) {
        float a = b1s[q];
        a = fmaf(px, w1s[q], a);
        a = fmaf(py, w1s[64 + q], a);
        a = fmaf(pz, w1s[128 + q], a);
        h1[q] = softplus_f(a);
    }

    // layer 2: 64 -> 64 softplus, fused with layer 3 (64 -> 1)
    float outv = b3s;
#pragma unroll 4
    for (int q = 0; q < 64; q++) {
        const float4* wrow = (const float4*)&w2t[q * 64];
        float a0 = b2s[q], a1 = 0.f, a2 = 0.f, a3 = 0.f;
#pragma unroll
        for (int k = 0; k < 16; k++) {
            float4 w = wrow[k];
            a0 = fmaf(h1[4 * k + 0], w.x, a0);
            a1 = fmaf(h1[4 * k + 1], w.y, a1);
            a2 = fmaf(h1[4 * k + 2], w.z, a2);
            a3 = fmaf(h1[4 * k + 3], w.w, a3);
        }
        float hv = softplus_f((a0 + a1) + (a2 + a3));
        outv = fmaf(hv, w3s[q], outv);
    }

    float nrm = sqrtf(fmaf(px, px, fmaf(py, py, pz * pz)));
    outp[ray * stride + j] = nrm - 0.8f + 0.1f * outv;
}

// ---------------- upsample: alpha -> weights -> inverse-CDF sampling -------
__global__ void upsample_kernel(int n, float s_i) {
    int r = blockIdx.x * blockDim.x + threadIdx.x;
    if (r >= NRAYS) return;
    const float* d  = g_d  + r * MAXS;
    const float* sd = g_sdf + r * MAXS;

    float cdf[129];
    float T = 1.0f, wsum = 0.0f, rawPrev = 0.0f;
    for (int j = 0; j < n - 1; j++) {
        float z0 = d[j], z1 = d[j + 1], s0 = sd[j], s1 = sd[j + 1];
        float mid = 0.5f * (s0 + s1);
        float raw = (s1 - s0) / (z1 - z0 + 1e-5f);
        float dv = fminf(rawPrev, raw);
        rawPrev = raw;
        dv = fminf(fmaxf(dv, -10.0f), 0.0f);
        float dist = z1 - z0;
        float pe = mid - dv * dist * 0.5f;
        float ne = mid + dv * dist * 0.5f;
        float pc = sigmoid_f(pe * s_i);
        float nc = sigmoid_f(ne * s_i);
        float alpha = (pc - nc + 1e-5f) / (pc + 1e-5f);
        float w = alpha * T;
        T *= (1.0f - alpha + 1e-10f);
        float wp = w + 1e-5f;
        wsum += wp;
        cdf[j + 1] = wp;  // stash raw weights
    }
    cdf[0] = 0.0f;
    float c = 0.0f;
    for (int j = 1; j <= n - 1; j++) {
        c += cdf[j] / wsum;   // pdf = (w+1e-5)/sum, cumsum
        cdf[j] = c;
    }

    for (int i = 0; i < 16; i++) {
        float u = (float)i / 15.0f;
        // searchsorted side='right' over cdf[0..n-1]: count of elements <= u
        int lo = 0, hi = n;
        while (lo < hi) {
            int m = (lo + hi) >> 1;
            if (cdf[m] <= u) lo = m + 1; else hi = m;
        }
        int below = lo - 1;
        if (below < 0) below = 0;
        if (below > n - 1) below = n - 1;
        int above = lo;
        if (above > n - 1) above = n - 1;
        float cb = cdf[below], ca = cdf[above];
        float bb = d[below],   ba = d[above];
        float den = ca - cb;
        if (den < 1e-5f) den = 1.0f;
        float t = (u - cb) / den;
        g_dfine[r * 16 + i] = bb + t * (ba - bb);
    }
}

// ---------------- stable merge of sorted (d,sdf) with 16 new samples -------
// jnp.argsort is stable: existing entries precede equal new entries.
// Merging back-to-front: on ties pop the NEW element first (higher index).
__global__ void merge_kernel(int n) {
    int r = blockIdx.x * blockDim.x + threadIdx.x;
    if (r >= NRAYS) return;
    float* d  = g_d  + r * MAXS;
    float* sd = g_sdf + r * MAXS;
    const float* fd = g_dfine + r * 16;
    const float* fs = g_sdff  + r * 16;
    int a = n - 1, b = 15, w = n + 15;
    while (b >= 0) {
        if (a >= 0 && d[a] > fd[b]) {
            d[w] = d[a]; sd[w] = sd[a]; a--;
        } else {
            d[w] = fd[b]; sd[w] = fs[b]; b--;
        }
        w--;
    }
}

// ---------------- final render: alpha compositing + radiance MLP -----------
__global__ void render_kernel(const float* __restrict__ o,
                              const float* __restrict__ sp,
                              const float* __restrict__ w1, const float* __restrict__ b1,
                              const float* __restrict__ w2, const float* __restrict__ b2,
                              float* __restrict__ out) {
    int r = blockIdx.x;
    int tid = threadIdx.x;
    __shared__ float dsh[128], cdfsh[128], alphash[127], visw[127];
    __shared__ float w1s[384], b1s[64], w2s[192], b2s[3];
    __shared__ float red0[128], red1[128], red2[128];

    for (int i = tid; i < 384; i += 128) w1s[i] = w1[i];
    for (int i = tid; i < 192; i += 128) w2s[i] = w2[i];
    if (tid < 64) b1s[tid] = b1[tid];
    if (tid < 3)  b2s[tid] = b2[tid];

    float s = sp[0];
    float dv = g_d[r * MAXS + tid];
    dsh[tid] = dv;
    cdfsh[tid] = sigmoid_f(g_sdf[r * MAXS + tid] * s);
    __syncthreads();

    if (tid < 127) {
        float a = (cdfsh[tid] - cdfsh[tid + 1]) / (cdfsh[tid] + 1e-10f);
        alphash[tid] = fmaxf(a, 0.0f);
    }
    __syncthreads();
    if (tid == 0) {
        float T = 1.0f;
        for (int j = 0; j < 127; j++) {
            visw[j] = alphash[j] * T;
            T *= (1.0f - alphash[j] + 1e-10f);
        }
    }
    __syncthreads();

    float rr = 0.f, gg = 0.f, bb = 0.f;
    if (tid < 127) {
        float dm = 0.5f * (dsh[tid] + dsh[tid + 1]);
        float ox = o[r * 3 + 0], oy = o[r * 3 + 1], oz = o[r * 3 + 2];
        float dx = g_dirs[r * 3 + 0], dy = g_dirs[r * 3 + 1], dz = g_dirs[r * 3 + 2];
        float x0 = fmaf(dm, dx, ox), x1 = fmaf(dm, dy, oy), x2 = fmaf(dm, dz, oz);
        float a0 = b2s[0], a1 = b2s[1], a2 = b2s[2];
#pragma unroll 8
        for (int j = 0; j < 64; j++) {
            float h = b1s[j];
            h = fmaf(x0, w1s[j], h);
            h = fmaf(x1, w1s[64 + j], h);
            h = fmaf(x2, w1s[128 + j], h);
            h = fmaf(dx, w1s[192 + j], h);
            h = fmaf(dy, w1s[256 + j], h);
            h = fmaf(dz, w1s[320 + j], h);
            h = softplus_f(h);
            a0 = fmaf(h, w2s[j * 3 + 0], a0);
            a1 = fmaf(h, w2s[j * 3 + 1], a1);
            a2 = fmaf(h, w2s[j * 3 + 2], a2);
        }
        float vw = visw[tid];
        rr = sigmoid_f(a0) * vw;
        gg = sigmoid_f(a1) * vw;
        bb = sigmoid_f(a2) * vw;
    }
    red0[tid] = rr; red1[tid] = gg; red2[tid] = bb;
    __syncthreads();
    for (int off = 64; off > 0; off >>= 1) {
        if (tid < off) {
            red0[tid] += red0[tid + off];
            red1[tid] += red1[tid + off];
            red2[tid] += red2[tid + off];
        }
        __syncthreads();
    }
    if (tid < 3) {
        float v = (tid == 0) ? red0[0] : (tid == 1) ? red1[0] : red2[0];
        out[r * 3 + tid] = v;
    }
}

// ---------------- launch ----------------------------------------------------
extern "C" void kernel_launch(void* const* d_in, const int* in_sizes, int n_in,
                              void* d_out, int out_size) {
    const float* rays_o = (const float*)d_in[0];
    const float* rays_d = (const float*)d_in[1];
    const float* nearp  = (const float*)d_in[2];
    const float* farp   = (const float*)d_in[3];
    const float* s_ptr  = (const float*)d_in[4];
    const float* sw1 = (const float*)d_in[5];
    const float* sb1 = (const float*)d_in[6];
    const float* sw2 = (const float*)d_in[7];
    const float* sb2 = (const float*)d_in[8];
    const float* sw3 = (const float*)d_in[9];
    const float* sb3 = (const float*)d_in[10];
    const float* rw1 = (const float*)d_in[11];
    const float* rb1 = (const float*)d_in[12];
    const float* rw2 = (const float*)d_in[13];
    const float* rb2 = (const float*)d_in[14];
    float* out = (float*)d_out;

    init_kernel<<<(NRAYS + 255) / 256, 256>>>(rays_d, nearp, farp);

    int npts_coarse = NRAYS * 64;
    sdf_kernel<<<(npts_coarse + 255) / 256, 256>>>(
        rays_o, sw1, sb1, sw2, sb2, sw3, sb3, 0, npts_coarse);

    int npts_fine = NRAYS * 16;
    for (int i = 0; i < 4; i++) {
        int n = 64 + 16 * i;
        float si = 64.0f * (float)(1 << i);
        upsample_kernel<<<(NRAYS + 255) / 256, 256>>>(n, si);
        sdf_kernel<<<(npts_fine + 255) / 256, 256>>>(
            rays_o, sw1, sb1, sw2, sb2, sw3, sb3, 1, npts_fine);
        merge_kernel<<<(NRAYS + 255) / 256, 256>>>(n);
    }

    render_kernel<<<NRAYS, 128>>>(rays_o, s_ptr, rw1, rb1, rw2, rb2, out);
}

// round 4
// speedup vs baseline: 1.8430x; 1.8430x over previous
#include <cuda_runtime.h>
#include <math.h>

#define NRAYS 16384
#define MAXS 128

// ---------------- scratch (device globals; no allocation allowed) ----------
__device__ float g_dirs[NRAYS * 3];
__device__ float g_dbuf[2][NRAYS * MAXS];
__device__ float g_sbuf[2][NRAYS * MAXS];
__device__ float g_dfine[NRAYS * 16];
__device__ float g_sdff[NRAYS * 16];

// ---------------- math helpers ---------------------------------------------
__device__ __forceinline__ float softplus_fast(float x) {
    // max(x,0) + log(1+exp(-|x|)) with HW MUFU exp/log
    float t = __expf(-fabsf(x));
    return fmaxf(x, 0.0f) + __logf(1.0f + t);
}
__device__ __forceinline__ float sigmoid_fast(float x) {
    return __fdividef(1.0f, 1.0f + __expf(-x));
}
__device__ __forceinline__ float sigmoid_precise(float x) {
    return 1.0f / (1.0f + expf(-x));
}

// ---------------- init: normalize dirs, fill coarse d ----------------------
__global__ void init_kernel(const float* __restrict__ rd,
                            const float* __restrict__ nearp,
                            const float* __restrict__ farp) {
    int r = blockIdx.x * blockDim.x + threadIdx.x;
    if (r >= NRAYS) return;
    float dx = rd[r * 3 + 0], dy = rd[r * 3 + 1], dz = rd[r * 3 + 2];
    float nrm = sqrtf(dx * dx + dy * dy + dz * dz);
    dx /= nrm; dy /= nrm; dz /= nrm;
    g_dirs[r * 3 + 0] = dx; g_dirs[r * 3 + 1] = dy; g_dirs[r * 3 + 2] = dz;
    float nr = nearp[r], fr = farp[r];
    for (int j = 0; j < 64; j++) {
        float t = (float)j / 63.0f;
        g_dbuf[0][r * MAXS + j] = nr * (1.0f - t) + fr * t;
    }
}

// ---------------- SDF MLP eval ----------------------------------------------
// mode 0: coarse (g_dbuf[0], stride 128, 64/ray -> g_sbuf[0])
// mode 1: fine   (g_dfine, stride 16, 16/ray -> g_sdff)
__global__ void sdf_kernel(const float* __restrict__ o,
                           const float* __restrict__ w1, const float* __restrict__ b1,
                           const float* __restrict__ w2, const float* __restrict__ b2,
                           const float* __restrict__ w3, const float* __restrict__ b3,
                           int mode, int npts) {
    __shared__ __align__(16) float w2t[64 * 64];  // w2t[j*64+k] = w2[k*64+j]
    __shared__ float w1s[192], b1s[64], b2s[64], w3s[64];
    __shared__ float b3s;

    int tid = threadIdx.x;
    for (int i = tid; i < 4096; i += blockDim.x) {
        w2t[(i & 63) * 64 + (i >> 6)] = w2[i];
    }
    for (int i = tid; i < 192; i += blockDim.x) w1s[i] = w1[i];
    if (tid < 64) { b1s[tid] = b1[tid]; b2s[tid] = b2[tid]; w3s[tid] = w3[tid]; }
    if (tid == 0) b3s = b3[0];
    __syncthreads();

    int p = blockIdx.x * blockDim.x + tid;
    if (p >= npts) return;

    const float* dvals = mode ? g_dfine : g_dbuf[0];
    float* outp        = mode ? g_sdff  : g_sbuf[0];
    int spr    = mode ? 16 : 64;
    int stride = mode ? 16 : MAXS;

    int ray = p / spr;
    int j   = p - ray * spr;
    float dv = dvals[ray * stride + j];

    float ox = o[ray * 3 + 0], oy = o[ray * 3 + 1], oz = o[ray * 3 + 2];
    float dx = g_dirs[ray * 3 + 0], dy = g_dirs[ray * 3 + 1], dz = g_dirs[ray * 3 + 2];
    float px = fmaf(dv, dx, ox), py = fmaf(dv, dy, oy), pz = fmaf(dv, dz, oz);

    // layer 1: 3 -> 64, softplus
    float h1[64];
#pragma unroll
    for (int q = 0; q < 64; q++) {
        float a = b1s[q];
        a = fmaf(px, w1s[q], a);
        a = fmaf(py, w1s[64 + q], a);
        a = fmaf(pz, w1s[128 + q], a);
        h1[q] = softplus_fast(a);
    }

    // layer 2: 64 -> 64 softplus, fused with layer 3 (64 -> 1)
    float outv = b3s;
#pragma unroll 4
    for (int q = 0; q < 64; q++) {
        const float4* wrow = (const float4*)&w2t[q * 64];
        float a0 = b2s[q], a1 = 0.f, a2 = 0.f, a3 = 0.f;
#pragma unroll
        for (int k = 0; k < 16; k++) {
            float4 w = wrow[k];
            a0 = fmaf(h1[4 * k + 0], w.x, a0);
            a1 = fmaf(h1[4 * k + 1], w.y, a1);
            a2 = fmaf(h1[4 * k + 2], w.z, a2);
            a3 = fmaf(h1[4 * k + 3], w.w, a3);
        }
        float hv = softplus_fast((a0 + a1) + (a2 + a3));
        outv = fmaf(hv, w3s[q], outv);
    }

    float nrm = sqrtf(fmaf(px, px, fmaf(py, py, pz * pz)));
    outp[ray * stride + j] = nrm - 0.8f + 0.1f * outv;
}

// ---------------- upsample: one warp per ray --------------------------------
#define UP_PAD 116
__global__ void upsample_kernel(int n, float s_i, int pp) {
    int gwarp = (blockIdx.x * blockDim.x + threadIdx.x) >> 5;
    int lane  = threadIdx.x & 31;
    int wib   = (threadIdx.x >> 5);
    __shared__ float scdf[8 * UP_PAD];
    if (gwarp >= NRAYS) return;

    const float* d  = g_dbuf[pp] + gwarp * MAXS;
    const float* sd = g_sbuf[pp] + gwarp * MAXS;
    int m = n - 1;
    int base = lane * 4;

    float dj[5], sj[5];
#pragma unroll
    for (int i = 0; i < 5; i++) {
        int idx = base + i;
        bool v = idx < n;
        dj[i] = v ? d[idx] : 1.0f;
        sj[i] = v ? sd[idx] : 0.0f;
    }

    float raw[4];
#pragma unroll
    for (int i = 0; i < 4; i++)
        raw[i] = (sj[i + 1] - sj[i]) / (dj[i + 1] - dj[i] + 1e-5f);

    float prevr = __shfl_up_sync(0xffffffffu, raw[3], 1);
    if (lane == 0) prevr = 0.0f;

    float alpha[4];
#pragma unroll
    for (int i = 0; i < 4; i++) {
        float dvv = fminf(prevr, raw[i]);
        prevr = raw[i];
        dvv = fminf(fmaxf(dvv, -10.0f), 0.0f);
        float mid  = 0.5f * (sj[i] + sj[i + 1]);
        float dist = dj[i + 1] - dj[i];
        float pe = mid - dvv * dist * 0.5f;
        float ne = mid + dvv * dist * 0.5f;
        float pc = sigmoid_precise(pe * s_i);
        float nc = sigmoid_precise(ne * s_i);
        alpha[i] = (pc - nc + 1e-5f) / (pc + 1e-5f);
    }

    // per-lane prefix products of (1-alpha+1e-10), masked outside [0,m)
    float Tloc[4], pl = 1.0f;
#pragma unroll
    for (int i = 0; i < 4; i++) {
        Tloc[i] = pl;
        float om = (base + i < m) ? (1.0f - alpha[i] + 1e-10f) : 1.0f;
        pl *= om;
    }
    // exclusive warp scan (product)
    float v = pl;
#pragma unroll
    for (int off = 1; off < 32; off <<= 1) {
        float t = __shfl_up_sync(0xffffffffu, v, off);
        if (lane >= off) v *= t;
    }
    float exp_ = __shfl_up_sync(0xffffffffu, v, 1);
    if (lane == 0) exp_ = 1.0f;

    // weights wp = alpha*T + 1e-5 on valid segs
    float wp[4], sl = 0.0f, sloc[4];
#pragma unroll
    for (int i = 0; i < 4; i++) {
        float T = exp_ * Tloc[i];
        wp[i] = (base + i < m) ? fmaf(alpha[i], T, 1e-5f) : 0.0f;
        sl += wp[i];
        sloc[i] = sl;
    }
    // warp reduce sum -> wsum; exclusive scan sum -> exs
    float tot = sl;
#pragma unroll
    for (int off = 16; off > 0; off >>= 1)
        tot += __shfl_xor_sync(0xffffffffu, tot, off);
    float vs = sl;
#pragma unroll
    for (int off = 1; off < 32; off <<= 1) {
        float t = __shfl_up_sync(0xffffffffu, vs, off);
        if (lane >= off) vs += t;
    }
    float exs = __shfl_up_sync(0xffffffffu, vs, 1);
    if (lane == 0) exs = 0.0f;

    float inv = 1.0f / tot;
    float* cdf = scdf + wib * UP_PAD;
    if (lane == 0) cdf[0] = 0.0f;
#pragma unroll
    for (int i = 0; i < 4; i++) {
        int j = base + i;
        if (j < m) cdf[j + 1] = (exs + sloc[i]) * inv;
    }
    __syncwarp();

    if (lane < 16) {
        float u = (float)lane / 15.0f;
        // searchsorted side='right' over cdf[0..n-1]
        int lo = 0, hi = n;
        while (lo < hi) {
            int mm = (lo + hi) >> 1;
            if (cdf[mm] <= u) lo = mm + 1; else hi = mm;
        }
        int below = lo - 1;
        if (below < 0) below = 0;
        if (below > n - 1) below = n - 1;
        int above = lo;
        if (above > n - 1) above = n - 1;
        float cb = cdf[below], ca = cdf[above];
        float bb = d[below],   ba = d[above];
        float den = ca - cb;
        if (den < 1e-5f) den = 1.0f;
        float t = (u - cb) / den;
        g_dfine[gwarp * 16 + lane] = bb + t * (ba - bb);
    }
}

// ---------------- parallel stable merge (rank & scatter), ping-pong ---------
__global__ void merge_kernel(int n, int pp) {
    int gwarp = (blockIdx.x * blockDim.x + threadIdx.x) >> 5;
    int lane  = threadIdx.x & 31;
    if (gwarp >= NRAYS) return;
    const float* d  = g_dbuf[pp] + gwarp * MAXS;
    const float* sd = g_sbuf[pp] + gwarp * MAXS;
    float* dd = g_dbuf[pp ^ 1] + gwarp * MAXS;
    float* ds = g_sbuf[pp ^ 1] + gwarp * MAXS;
    const float* fd = g_dfine + gwarp * 16;
    const float* fs = g_sdff  + gwarp * 16;

    if (lane < 16) {
        float v = fd[lane];
        int lo = 0, hi = n;                // count old <= v
        while (lo < hi) { int mm = (lo + hi) >> 1; if (d[mm] <= v) lo = mm + 1; else hi = mm; }
        dd[lo + lane] = v;
        ds[lo + lane] = fs[lane];
    }
    for (int a = lane; a < n; a += 32) {
        float v = d[a];
        int lo = 0, hi = 16;               // count new < v
        while (lo < hi) { int mm = (lo + hi) >> 1; if (fd[mm] < v) lo = mm + 1; else hi = mm; }
        dd[a + lo] = v;
        ds[a + lo] = sd[a];
    }
}

// ---------------- final render: compositing + radiance MLP ------------------
__global__ void render_kernel(const float* __restrict__ o,
                              const float* __restrict__ sp,
                              const float* __restrict__ w1, const float* __restrict__ b1,
                              const float* __restrict__ w2, const float* __restrict__ b2,
                              float* __restrict__ out) {
    int r = blockIdx.x;
    int tid = threadIdx.x;
    __shared__ float dsh[128], cdfsh[128], alphash[128], scan[128];
    __shared__ float w1s[384], b1s[64], w2s[192], b2s[3];
    __shared__ float red0[128], red1[128], red2[128];

    for (int i = tid; i < 384; i += 128) w1s[i] = w1[i];
    for (int i = tid; i < 192; i += 128) w2s[i] = w2[i];
    if (tid < 64) b1s[tid] = b1[tid];
    if (tid < 3)  b2s[tid] = b2[tid];

    float s = sp[0];
    float dv = g_dbuf[0][r * MAXS + tid];
    dsh[tid] = dv;
    cdfsh[tid] = sigmoid_precise(g_sbuf[0][r * MAXS + tid] * s);
    __syncthreads();

    float a = 0.0f;
    if (tid < 127)
        a = fmaxf((cdfsh[tid] - cdfsh[tid + 1]) / (cdfsh[tid] + 1e-10f), 0.0f);
    alphash[tid] = a;
    __syncthreads();                       // <-- was missing: cross-warp race
    // cumprod of shifted = [1, 1-a0+eps, 1-a1+eps, ...] (inclusive)
    scan[tid] = (tid == 0) ? 1.0f : (1.0f - alphash[tid - 1] + 1e-10f);
    __syncthreads();
#pragma unroll
    for (int off = 1; off < 128; off <<= 1) {
        float t = (tid >= off) ? scan[tid - off] : 1.0f;
        __syncthreads();
        scan[tid] *= t;
        __syncthreads();
    }

    float rr = 0.f, gg = 0.f, bb = 0.f;
    if (tid < 127) {
        float vw = alphash[tid] * scan[tid];
        float dm = 0.5f * (dsh[tid] + dsh[tid + 1]);
        float ox = o[r * 3 + 0], oy = o[r * 3 + 1], oz = o[r * 3 + 2];
        float dx = g_dirs[r * 3 + 0], dy = g_dirs[r * 3 + 1], dz = g_dirs[r * 3 + 2];
        float x0 = fmaf(dm, dx, ox), x1 = fmaf(dm, dy, oy), x2 = fmaf(dm, dz, oz);
        float a0 = b2s[0], a1 = b2s[1], a2 = b2s[2];
#pragma unroll 8
        for (int j = 0; j < 64; j++) {
            float h = b1s[j];
            h = fmaf(x0, w1s[j], h);
            h = fmaf(x1, w1s[64 + j], h);
            h = fmaf(x2, w1s[128 + j], h);
            h = fmaf(dx, w1s[192 + j], h);
            h = fmaf(dy, w1s[256 + j], h);
            h = fmaf(dz, w1s[320 + j], h);
            h = softplus_fast(h);
            a0 = fmaf(h, w2s[j * 3 + 0], a0);
            a1 = fmaf(h, w2s[j * 3 + 1], a1);
            a2 = fmaf(h, w2s[j * 3 + 2], a2);
        }
        rr = sigmoid_fast(a0) * vw;
        gg = sigmoid_fast(a1) * vw;
        bb = sigmoid_fast(a2) * vw;
    }
    red0[tid] = rr; red1[tid] = gg; red2[tid] = bb;
    __syncthreads();
    for (int off = 64; off > 0; off >>= 1) {
        if (tid < off) {
            red0[tid] += red0[tid + off];
            red1[tid] += red1[tid + off];
            red2[tid] += red2[tid + off];
        }
        __syncthreads();
    }
    if (tid < 3) {
        float v = (tid == 0) ? red0[0] : (tid == 1) ? red1[0] : red2[0];
        out[r * 3 + tid] = v;
    }
}

// ---------------- launch ----------------------------------------------------
extern "C" void kernel_launch(void* const* d_in, const int* in_sizes, int n_in,
                              void* d_out, int out_size) {
    const float* rays_o = (const float*)d_in[0];
    const float* rays_d = (const float*)d_in[1];
    const float* nearp  = (const float*)d_in[2];
    const float* farp   = (const float*)d_in[3];
    const float* s_ptr  = (const float*)d_in[4];
    const float* sw1 = (const float*)d_in[5];
    const float* sb1 = (const float*)d_in[6];
    const float* sw2 = (const float*)d_in[7];
    const float* sb2 = (const float*)d_in[8];
    const float* sw3 = (const float*)d_in[9];
    const float* sb3 = (const float*)d_in[10];
    const float* rw1 = (const float*)d_in[11];
    const float* rb1 = (const float*)d_in[12];
    const float* rw2 = (const float*)d_in[13];
    const float* rb2 = (const float*)d_in[14];
    float* out = (float*)d_out;

    init_kernel<<<(NRAYS + 255) / 256, 256>>>(rays_d, nearp, farp);

    int npts_coarse = NRAYS * 64;
    sdf_kernel<<<(npts_coarse + 255) / 256, 256>>>(
        rays_o, sw1, sb1, sw2, sb2, sw3, sb3, 0, npts_coarse);

    int npts_fine = NRAYS * 16;
    int warps_grid = (NRAYS * 32 + 255) / 256;   // one warp per ray
    int pp = 0;
    for (int i = 0; i < 4; i++) {
        int n = 64 + 16 * i;
        float si = 64.0f * (float)(1 << i);
        upsample_kernel<<<warps_grid, 256>>>(n, si, pp);
        sdf_kernel<<<(npts_fine + 255) / 256, 256>>>(
            rays_o, sw1, sb1, sw2, sb2, sw3, sb3, 1, npts_fine);
        merge_kernel<<<warps_grid, 256>>>(n, pp);
        pp ^= 1;
    }
    // after 4 flips pp == 0: final data in buffer 0
    render_kernel<<<NRAYS, 128>>>(rays_o, s_ptr, rw1, rb1, rw2, rb2, out);
}

// round 5
// speedup vs baseline: 2.0445x; 1.1093x over previous
#include <cuda_runtime.h>
#include <math.h>

#define NRAYS 16384
#define MAXS 128

// ---------------- scratch (device globals; no allocation allowed) ----------
__device__ float g_dirs[NRAYS * 3];
__device__ float g_dbuf[2][NRAYS * MAXS];
__device__ float g_sbuf[2][NRAYS * MAXS];
__device__ float g_dfine[NRAYS * 16];
__device__ float g_sdff[NRAYS * 16];

// ---------------- math helpers ---------------------------------------------
__device__ __forceinline__ float softplus_fast(float x) {
    float t = __expf(-fabsf(x));
    return fmaxf(x, 0.0f) + __logf(1.0f + t);
}
__device__ __forceinline__ float sigmoid_fast(float x) {
    return __fdividef(1.0f, 1.0f + __expf(-x));
}
__device__ __forceinline__ float sigmoid_precise(float x) {
    return 1.0f / (1.0f + expf(-x));
}

// ---------------- init: normalize dirs, fill coarse d ----------------------
__global__ void init_kernel(const float* __restrict__ rd,
                            const float* __restrict__ nearp,
                            const float* __restrict__ farp) {
    int r = blockIdx.x * blockDim.x + threadIdx.x;
    if (r >= NRAYS) return;
    float dx = rd[r * 3 + 0], dy = rd[r * 3 + 1], dz = rd[r * 3 + 2];
    float nrm = sqrtf(dx * dx + dy * dy + dz * dz);
    dx /= nrm; dy /= nrm; dz /= nrm;
    g_dirs[r * 3 + 0] = dx; g_dirs[r * 3 + 1] = dy; g_dirs[r * 3 + 2] = dz;
    float nr = nearp[r], fr = farp[r];
    for (int j = 0; j < 64; j++) {
        float t = (float)j / 63.0f;
        g_dbuf[0][r * MAXS + j] = nr * (1.0f - t) + fr * t;
    }
}

// ---------------- SDF MLP eval: 2 points per thread (same ray) --------------
// mode 0: coarse (g_dbuf[0], stride 128, 64/ray -> g_sbuf[0])
// mode 1: fine   (g_dfine, stride 16, 16/ray -> g_sdff)
__global__ void __launch_bounds__(256)
sdf_kernel(const float* __restrict__ o,
           const float* __restrict__ w1, const float* __restrict__ b1,
           const float* __restrict__ w2, const float* __restrict__ b2,
           const float* __restrict__ w3, const float* __restrict__ b3,
           int mode, int npts) {
    __shared__ __align__(16) float w2t[64 * 64];  // w2t[j*64+k] = w2[k*64+j]
    __shared__ float w1s[192], b1s[64], b2s[64], w3s[64];
    __shared__ float b3s;

    int tid = threadIdx.x;
    for (int i = tid; i < 4096; i += blockDim.x) {
        w2t[(i & 63) * 64 + (i >> 6)] = w2[i];
    }
    for (int i = tid; i < 192; i += blockDim.x) w1s[i] = w1[i];
    if (tid < 64) { b1s[tid] = b1[tid]; b2s[tid] = b2[tid]; w3s[tid] = w3[tid]; }
    if (tid == 0) b3s = b3[0];
    __syncthreads();

    int p0 = 2 * (blockIdx.x * blockDim.x + tid);
    if (p0 >= npts) return;

    const float* dvals = mode ? g_dfine : g_dbuf[0];
    float* outp        = mode ? g_sdff  : g_sbuf[0];
    int spr    = mode ? 16 : 64;
    int stride = mode ? 16 : MAXS;

    // p0 even, spr even -> p0 and p0+1 always share a ray
    int ray = p0 / spr;
    int j0  = p0 - ray * spr;
    float dv0 = dvals[ray * stride + j0];
    float dv1 = dvals[ray * stride + j0 + 1];

    float ox = o[ray * 3 + 0], oy = o[ray * 3 + 1], oz = o[ray * 3 + 2];
    float dx = g_dirs[ray * 3 + 0], dy = g_dirs[ray * 3 + 1], dz = g_dirs[ray * 3 + 2];
    float pax = fmaf(dv0, dx, ox), pay = fmaf(dv0, dy, oy), paz = fmaf(dv0, dz, oz);
    float pbx = fmaf(dv1, dx, ox), pby = fmaf(dv1, dy, oy), pbz = fmaf(dv1, dz, oz);

    // layer 1: 3 -> 64, softplus (both points)
    float h1a[64], h1b[64];
#pragma unroll
    for (int q = 0; q < 64; q++) {
        float wq0 = w1s[q], wq1 = w1s[64 + q], wq2 = w1s[128 + q], bq = b1s[q];
        float a = bq, b = bq;
        a = fmaf(pax, wq0, a);  b = fmaf(pbx, wq0, b);
        a = fmaf(pay, wq1, a);  b = fmaf(pby, wq1, b);
        a = fmaf(paz, wq2, a);  b = fmaf(pbz, wq2, b);
        h1a[q] = softplus_fast(a);
        h1b[q] = softplus_fast(b);
    }

    // layer 2: 64 -> 64 softplus, fused layer 3 (64 -> 1), both points share LDS
    float outa = b3s, outb = b3s;
#pragma unroll 4
    for (int q = 0; q < 64; q++) {
        const float4* wrow = (const float4*)&w2t[q * 64];
        float a0 = b2s[q], a1 = 0.f, a2 = 0.f, a3 = 0.f;
        float c0 = b2s[q], c1 = 0.f, c2 = 0.f, c3 = 0.f;
#pragma unroll
        for (int k = 0; k < 16; k++) {
            float4 w = wrow[k];
            a0 = fmaf(h1a[4 * k + 0], w.x, a0);
            a1 = fmaf(h1a[4 * k + 1], w.y, a1);
            a2 = fmaf(h1a[4 * k + 2], w.z, a2);
            a3 = fmaf(h1a[4 * k + 3], w.w, a3);
            c0 = fmaf(h1b[4 * k + 0], w.x, c0);
            c1 = fmaf(h1b[4 * k + 1], w.y, c1);
            c2 = fmaf(h1b[4 * k + 2], w.z, c2);
            c3 = fmaf(h1b[4 * k + 3], w.w, c3);
        }
        float w3q = w3s[q];
        float hva = softplus_fast((a0 + a1) + (a2 + a3));
        float hvb = softplus_fast((c0 + c1) + (c2 + c3));
        outa = fmaf(hva, w3q, outa);
        outb = fmaf(hvb, w3q, outb);
    }

    float na = sqrtf(fmaf(pax, pax, fmaf(pay, pay, paz * paz)));
    float nb = sqrtf(fmaf(pbx, pbx, fmaf(pby, pby, pbz * pbz)));
    outp[ray * stride + j0]     = na - 0.8f + 0.1f * outa;
    outp[ray * stride + j0 + 1] = nb - 0.8f + 0.1f * outb;
}

// ---------------- upsample: one warp per ray --------------------------------
#define UP_PAD 116
__global__ void upsample_kernel(int n, float s_i, int pp) {
    int gwarp = (blockIdx.x * blockDim.x + threadIdx.x) >> 5;
    int lane  = threadIdx.x & 31;
    int wib   = (threadIdx.x >> 5);
    __shared__ float scdf[8 * UP_PAD];
    if (gwarp >= NRAYS) return;

    const float* d  = g_dbuf[pp] + gwarp * MAXS;
    const float* sd = g_sbuf[pp] + gwarp * MAXS;
    int m = n - 1;
    int base = lane * 4;

    float dj[5], sj[5];
#pragma unroll
    for (int i = 0; i < 5; i++) {
        int idx = base + i;
        bool v = idx < n;
        dj[i] = v ? d[idx] : 1.0f;
        sj[i] = v ? sd[idx] : 0.0f;
    }

    float raw[4];
#pragma unroll
    for (int i = 0; i < 4; i++)
        raw[i] = (sj[i + 1] - sj[i]) / (dj[i + 1] - dj[i] + 1e-5f);

    float prevr = __shfl_up_sync(0xffffffffu, raw[3], 1);
    if (lane == 0) prevr = 0.0f;

    float alpha[4];
#pragma unroll
    for (int i = 0; i < 4; i++) {
        float dvv = fminf(prevr, raw[i]);
        prevr = raw[i];
        dvv = fminf(fmaxf(dvv, -10.0f), 0.0f);
        float mid  = 0.5f * (sj[i] + sj[i + 1]);
        float dist = dj[i + 1] - dj[i];
        float pe = mid - dvv * dist * 0.5f;
        float ne = mid + dvv * dist * 0.5f;
        float pc = sigmoid_precise(pe * s_i);
        float nc = sigmoid_precise(ne * s_i);
        alpha[i] = (pc - nc + 1e-5f) / (pc + 1e-5f);
    }

    float Tloc[4], pl = 1.0f;
#pragma unroll
    for (int i = 0; i < 4; i++) {
        Tloc[i] = pl;
        float om = (base + i < m) ? (1.0f - alpha[i] + 1e-10f) : 1.0f;
        pl *= om;
    }
    float v = pl;
#pragma unroll
    for (int off = 1; off < 32; off <<= 1) {
        float t = __shfl_up_sync(0xffffffffu, v, off);
        if (lane >= off) v *= t;
    }
    float exp_ = __shfl_up_sync(0xffffffffu, v, 1);
    if (lane == 0) exp_ = 1.0f;

    float wp[4], sl = 0.0f, sloc[4];
#pragma unroll
    for (int i = 0; i < 4; i++) {
        float T = exp_ * Tloc[i];
        wp[i] = (base + i < m) ? fmaf(alpha[i], T, 1e-5f) : 0.0f;
        sl += wp[i];
        sloc[i] = sl;
    }
    float tot = sl;
#pragma unroll
    for (int off = 16; off > 0; off >>= 1)
        tot += __shfl_xor_sync(0xffffffffu, tot, off);
    float vs = sl;
#pragma unroll
    for (int off = 1; off < 32; off <<= 1) {
        float t = __shfl_up_sync(0xffffffffu, vs, off);
        if (lane >= off) vs += t;
    }
    float exs = __shfl_up_sync(0xffffffffu, vs, 1);
    if (lane == 0) exs = 0.0f;

    float inv = 1.0f / tot;
    float* cdf = scdf + wib * UP_PAD;
    if (lane == 0) cdf[0] = 0.0f;
#pragma unroll
    for (int i = 0; i < 4; i++) {
        int j = base + i;
        if (j < m) cdf[j + 1] = (exs + sloc[i]) * inv;
    }
    __syncwarp();

    if (lane < 16) {
        float u = (float)lane / 15.0f;
        int lo = 0, hi = n;
        while (lo < hi) {
            int mm = (lo + hi) >> 1;
            if (cdf[mm] <= u) lo = mm + 1; else hi = mm;
        }
        int below = lo - 1;
        if (below < 0) below = 0;
        if (below > n - 1) below = n - 1;
        int above = lo;
        if (above > n - 1) above = n - 1;
        float cb = cdf[below], ca = cdf[above];
        float bb = d[below],   ba = d[above];
        float den = ca - cb;
        if (den < 1e-5f) den = 1.0f;
        float t = (u - cb) / den;
        g_dfine[gwarp * 16 + lane] = bb + t * (ba - bb);
    }
}

// ---------------- parallel stable merge (rank & scatter), ping-pong ---------
__global__ void merge_kernel(int n, int pp) {
    int gwarp = (blockIdx.x * blockDim.x + threadIdx.x) >> 5;
    int lane  = threadIdx.x & 31;
    if (gwarp >= NRAYS) return;
    const float* d  = g_dbuf[pp] + gwarp * MAXS;
    const float* sd = g_sbuf[pp] + gwarp * MAXS;
    float* dd = g_dbuf[pp ^ 1] + gwarp * MAXS;
    float* ds = g_sbuf[pp ^ 1] + gwarp * MAXS;
    const float* fd = g_dfine + gwarp * 16;
    const float* fs = g_sdff  + gwarp * 16;

    if (lane < 16) {
        float v = fd[lane];
        int lo = 0, hi = n;                // count old <= v
        while (lo < hi) { int mm = (lo + hi) >> 1; if (d[mm] <= v) lo = mm + 1; else hi = mm; }
        dd[lo + lane] = v;
        ds[lo + lane] = fs[lane];
    }
    for (int a = lane; a < n; a += 32) {
        float v = d[a];
        int lo = 0, hi = 16;               // count new < v
        while (lo < hi) { int mm = (lo + hi) >> 1; if (fd[mm] < v) lo = mm + 1; else hi = mm; }
        dd[a + lo] = v;
        ds[a + lo] = sd[a];
    }
}

// ---------------- final render: compositing + radiance MLP ------------------
__global__ void render_kernel(const float* __restrict__ o,
                              const float* __restrict__ sp,
                              const float* __restrict__ w1, const float* __restrict__ b1,
                              const float* __restrict__ w2, const float* __restrict__ b2,
                              float* __restrict__ out) {
    int r = blockIdx.x;
    int tid = threadIdx.x;
    __shared__ float dsh[128], cdfsh[128], alphash[128], scan[128];
    __shared__ float w1s[384], b1s[64], w2s[192], b2s[3];
    __shared__ float red0[128], red1[128], red2[128];

    for (int i = tid; i < 384; i += 128) w1s[i] = w1[i];
    for (int i = tid; i < 192; i += 128) w2s[i] = w2[i];
    if (tid < 64) b1s[tid] = b1[tid];
    if (tid < 3)  b2s[tid] = b2[tid];

    float s = sp[0];
    float dv = g_dbuf[0][r * MAXS + tid];
    dsh[tid] = dv;
    cdfsh[tid] = sigmoid_precise(g_sbuf[0][r * MAXS + tid] * s);
    __syncthreads();

    float a = 0.0f;
    if (tid < 127)
        a = fmaxf((cdfsh[tid] - cdfsh[tid + 1]) / (cdfsh[tid] + 1e-10f), 0.0f);
    alphash[tid] = a;
    __syncthreads();
    scan[tid] = (tid == 0) ? 1.0f : (1.0f - alphash[tid - 1] + 1e-10f);
    __syncthreads();
#pragma unroll
    for (int off = 1; off < 128; off <<= 1) {
        float t = (tid >= off) ? scan[tid - off] : 1.0f;
        __syncthreads();
        scan[tid] *= t;
        __syncthreads();
    }

    float rr = 0.f, gg = 0.f, bb = 0.f;
    if (tid < 127) {
        float vw = alphash[tid] * scan[tid];
        float dm = 0.5f * (dsh[tid] + dsh[tid + 1]);
        float ox = o[r * 3 + 0], oy = o[r * 3 + 1], oz = o[r * 3 + 2];
        float dx = g_dirs[r * 3 + 0], dy = g_dirs[r * 3 + 1], dz = g_dirs[r * 3 + 2];
        float x0 = fmaf(dm, dx, ox), x1 = fmaf(dm, dy, oy), x2 = fmaf(dm, dz, oz);
        float a0 = b2s[0], a1 = b2s[1], a2 = b2s[2];
#pragma unroll 8
        for (int j = 0; j < 64; j++) {
            float h = b1s[j];
            h = fmaf(x0, w1s[j], h);
            h = fmaf(x1, w1s[64 + j], h);
            h = fmaf(x2, w1s[128 + j], h);
            h = fmaf(dx, w1s[192 + j], h);
            h = fmaf(dy, w1s[256 + j], h);
            h = fmaf(dz, w1s[320 + j], h);
            h = softplus_fast(h);
            a0 = fmaf(h, w2s[j * 3 + 0], a0);
            a1 = fmaf(h, w2s[j * 3 + 1], a1);
            a2 = fmaf(h, w2s[j * 3 + 2], a2);
        }
        rr = sigmoid_fast(a0) * vw;
        gg = sigmoid_fast(a1) * vw;
        bb = sigmoid_fast(a2) * vw;
    }
    red0[tid] = rr; red1[tid] = gg; red2[tid] = bb;
    __syncthreads();
    for (int off = 64; off > 0; off >>= 1) {
        if (tid < off) {
            red0[tid] += red0[tid + off];
            red1[tid] += red1[tid + off];
            red2[tid] += red2[tid + off];
        }
        __syncthreads();
    }
    if (tid < 3) {
        float v = (tid == 0) ? red0[0] : (tid == 1) ? red1[0] : red2[0];
        out[r * 3 + tid] = v;
    }
}

// ---------------- launch ----------------------------------------------------
extern "C" void kernel_launch(void* const* d_in, const int* in_sizes, int n_in,
                              void* d_out, int out_size) {
    const float* rays_o = (const float*)d_in[0];
    const float* rays_d = (const float*)d_in[1];
    const float* nearp  = (const float*)d_in[2];
    const float* farp   = (const float*)d_in[3];
    const float* s_ptr  = (const float*)d_in[4];
    const float* sw1 = (const float*)d_in[5];
    const float* sb1 = (const float*)d_in[6];
    const float* sw2 = (const float*)d_in[7];
    const float* sb2 = (const float*)d_in[8];
    const float* sw3 = (const float*)d_in[9];
    const float* sb3 = (const float*)d_in[10];
    const float* rw1 = (const float*)d_in[11];
    const float* rb1 = (const float*)d_in[12];
    const float* rw2 = (const float*)d_in[13];
    const float* rb2 = (const float*)d_in[14];
    float* out = (float*)d_out;

    init_kernel<<<(NRAYS + 255) / 256, 256>>>(rays_d, nearp, farp);

    int npts_coarse = NRAYS * 64;
    int thr_coarse = npts_coarse / 2;
    sdf_kernel<<<(thr_coarse + 255) / 256, 256>>>(
        rays_o, sw1, sb1, sw2, sb2, sw3, sb3, 0, npts_coarse);

    int npts_fine = NRAYS * 16;
    int thr_fine = npts_fine / 2;
    int warps_grid = (NRAYS * 32 + 255) / 256;   // one warp per ray
    int pp = 0;
    for (int i = 0; i < 4; i++) {
        int n = 64 + 16 * i;
        float si = 64.0f * (float)(1 << i);
        upsample_kernel<<<warps_grid, 256>>>(n, si, pp);
        sdf_kernel<<<(thr_fine + 255) / 256, 256>>>(
            rays_o, sw1, sb1, sw2, sb2, sw3, sb3, 1, npts_fine);
        merge_kernel<<<warps_grid, 256>>>(n, pp);
        pp ^= 1;
    }
    // after 4 flips pp == 0: final data in buffer 0
    render_kernel<<<NRAYS, 128>>>(rays_o, s_ptr, rw1, rb1, rw2, rb2, out);
}